// round 3
// baseline (speedup 1.0000x reference)
#include <cuda_runtime.h>
#include <math.h>

#define W_ 256
#define H_ 256
#define NMAX 768
#define CUT_SIGMA 5.5412636f   // log(255): alpha >= 1/255  <=>  sigma <= log(255)

// depth-sorted gaussian data (written directly at rank by fused kernel)
__device__ float4 g_A[NMAX];   // mx, my, 0.5*conicA, 0.5*conicC
__device__ float4 g_B[NMAX];   // conicB, bias(=-log op), r, g
__device__ float  g_bv[NMAX];  // blue
__device__ float4 g_bb[NMAX];  // x0, x1, y0, y1

// Fused: preprocess + stable rank (scanning raw z from input) + scatter at rank.
__global__ void gs_prep_sort(const float* __restrict__ means,
                             const float* __restrict__ quats,
                             const float* __restrict__ scales,
                             const float* __restrict__ opac_in,
                             const float* __restrict__ rgbs,
                             int n) {
    int i = blockIdx.x * blockDim.x + threadIdx.x;
    if (i >= n) return;

    // ---- stable rank by camera-space z (tz = z + 8, monotone in raw z) ----
    float zi = __ldg(&means[i*3+2]);
    int rank = 0;
    #pragma unroll 8
    for (int j = 0; j < n; j++) {
        float zj = __ldg(&means[j*3+2]);
        rank += (zj < zi || (zj == zi && j < i)) ? 1 : 0;
    }

    // ---- preprocess ----
    float qw = quats[i*4+0], qx = quats[i*4+1], qy = quats[i*4+2], qz = quats[i*4+3];
    float inv = rsqrtf(qw*qw + qx*qx + qy*qy + qz*qz);
    float w = qw*inv, x = qx*inv, y = qy*inv, z = qz*inv;

    float R00 = 1.f - 2.f*(y*y + z*z), R01 = 2.f*(x*y - w*z), R02 = 2.f*(x*z + w*y);
    float R10 = 2.f*(x*y + w*z), R11 = 1.f - 2.f*(x*x + z*z), R12 = 2.f*(y*z - w*x);
    float R20 = 2.f*(x*z - w*y), R21 = 2.f*(y*z + w*x), R22 = 1.f - 2.f*(x*x + y*y);

    float sx = scales[i*3+0], sy = scales[i*3+1], sz = scales[i*3+2];
    float s0 = sx*sx, s1 = sy*sy, s2 = sz*sz;

    float C00 = R00*R00*s0 + R01*R01*s1 + R02*R02*s2;
    float C01 = R00*R10*s0 + R01*R11*s1 + R02*R12*s2;
    float C02 = R00*R20*s0 + R01*R21*s1 + R02*R22*s2;
    float C11 = R10*R10*s0 + R11*R11*s1 + R12*R12*s2;
    float C12 = R10*R20*s0 + R11*R21*s1 + R12*R22*s2;
    float C22 = R20*R20*s0 + R21*R21*s1 + R22*R22*s2;

    float tx = means[i*3+0], ty = means[i*3+1], tz = zi + 8.0f;
    const float f = 128.0f;
    float iz = 1.0f / tz;
    float j00 = f * iz;
    float j02 = -f * tx * iz * iz;
    float j12 = -f * ty * iz * iz;

    float a = j00*j00*C00 + 2.f*j00*j02*C02 + j02*j02*C22 + 0.3f;
    float b = j00*j00*C01 + j00*j12*C02 + j02*j00*C12 + j02*j12*C22;
    float c = j00*j00*C11 + 2.f*j00*j12*C12 + j12*j12*C22 + 0.3f;

    float det = a*c - b*b;
    float idet = 1.0f / det;
    float cA = c * idet, cB = -b * idet, cC = a * idet;

    float mx = f * tx * iz + 128.0f;
    float my = f * ty * iz + 128.0f;

    float op = 1.0f / (1.0f + __expf(-opac_in[i]));
    float cr = 1.0f / (1.0f + __expf(-rgbs[i*3+0]));
    float cg = 1.0f / (1.0f + __expf(-rgbs[i*3+1]));
    float cb = 1.0f / (1.0f + __expf(-rgbs[i*3+2]));

    float bias = -__logf(op);
    float tcut = CUT_SIGMA - bias;
    float ex, ey;
    if (tcut > 0.0f) {
        ex = sqrtf(2.0f * tcut * a) + 0.5f;
        ey = sqrtf(2.0f * tcut * c) + 0.5f;
    } else {
        ex = -1e30f; ey = -1e30f;
    }

    g_A[rank]  = make_float4(mx, my, 0.5f * cA, 0.5f * cC);
    g_B[rank]  = make_float4(cB, bias, cr, cg);
    g_bv[rank] = cb;
    g_bb[rank] = make_float4(mx - ex, mx + ex, my - ey, my + ey);
}

// 16x16 pixel tile per block; 16x8 threads; each thread does rows ty and ty+8.
__global__ __launch_bounds__(128) void gs_render(float* __restrict__ out, int n) {
    __shared__ float4 sA[NMAX];
    __shared__ float4 sB[NMAX];
    __shared__ float  sBV[NMAX];
    __shared__ int s_wcnt[4];
    __shared__ int s_woff[4];
    __shared__ int s_cnt;

    const int tx = threadIdx.x, ty = threadIdx.y;
    const int tid = ty * 16 + tx;
    const int warp = tid >> 5, lane = tid & 31;
    const int px0 = blockIdx.x * 16, py0 = blockIdx.y * 16;

    const float tlx = px0 + 0.5f,  thx = px0 + 15.5f;
    const float tly = py0 + 0.5f,  thy = py0 + 15.5f;

    // pass 1: per-warp counts over contiguous chunks
    const int nIter = (n + 127) / 128;
    const int beg = warp * nIter * 32;
    int cnt = 0;
    for (int it = 0; it < nIter; it++) {
        int g = beg + it * 32 + lane;
        bool pred = false;
        if (g < n) {
            float4 bb = g_bb[g];
            pred = (bb.y >= tlx) & (bb.x <= thx) & (bb.w >= tly) & (bb.z <= thy);
        }
        cnt += __popc(__ballot_sync(0xffffffffu, pred));
    }
    if (lane == 0) s_wcnt[warp] = cnt;
    __syncthreads();
    if (tid == 0) {
        int o = 0;
        #pragma unroll
        for (int w = 0; w < 4; w++) { s_woff[w] = o; o += s_wcnt[w]; }
        s_cnt = o;
    }
    __syncthreads();

    // pass 2: compact + stage directly into shared
    int off = s_woff[warp];
    for (int it = 0; it < nIter; it++) {
        int g = beg + it * 32 + lane;
        bool pred = false;
        if (g < n) {
            float4 bb = g_bb[g];
            pred = (bb.y >= tlx) & (bb.x <= thx) & (bb.w >= tly) & (bb.z <= thy);
        }
        unsigned m = __ballot_sync(0xffffffffu, pred);
        if (pred) {
            int slot = off + __popc(m & ((1u << lane) - 1u));
            sA[slot]  = g_A[g];
            sB[slot]  = g_B[g];
            sBV[slot] = g_bv[g];
        }
        off += __popc(m);
    }
    __syncthreads();
    const int tcnt = s_cnt;

    const float pxc  = px0 + tx + 0.5f;
    const float pyc0 = py0 + ty + 0.5f;
    const float pyc1 = pyc0 + 8.0f;

    float T0 = 1.0f, r0 = 0.0f, g0 = 0.0f, b0 = 0.0f;
    float T1 = 1.0f, r1 = 0.0f, g1 = 0.0f, b1 = 0.0f;

    for (int k = 0; k < tcnt; k++) {
        float4 A = sA[k];
        float4 B = sB[k];
        float dx  = pxc  - A.x;
        float dy0 = pyc0 - A.y;
        float dy1 = pyc1 - A.y;
        float base = fmaf(A.z, dx*dx, B.y);
        float bxdx = B.x * dx;
        float sg0 = fmaf(A.w, dy0*dy0, fmaf(bxdx, dy0, base));
        float sg1 = fmaf(A.w, dy1*dy1, fmaf(bxdx, dy1, base));
        if (sg0 <= CUT_SIGMA) {
            float al = fminf(0.999f, __expf(-sg0));
            float wt = T0 * al;
            float bv = sBV[k];
            r0 = fmaf(wt, B.z, r0);
            g0 = fmaf(wt, B.w, g0);
            b0 = fmaf(wt, bv,  b0);
            T0 -= wt;
        }
        if (sg1 <= CUT_SIGMA) {
            float al = fminf(0.999f, __expf(-sg1));
            float wt = T1 * al;
            float bv = sBV[k];
            r1 = fmaf(wt, B.z, r1);
            g1 = fmaf(wt, B.w, g1);
            b1 = fmaf(wt, bv,  b1);
            T1 -= wt;
        }
        if (T0 < 2e-6f && T1 < 2e-6f) break;
    }

    int p0 = (py0 + ty) * W_ + (px0 + tx);
    int p1 = p0 + 8 * W_;
    out[3*p0 + 0] = r0;  out[3*p0 + 1] = g0;  out[3*p0 + 2] = b0;
    out[3*p1 + 0] = r1;  out[3*p1 + 1] = g1;  out[3*p1 + 2] = b1;
}

extern "C" void kernel_launch(void* const* d_in, const int* in_sizes, int n_in,
                              void* d_out, int out_size) {
    const float* means  = (const float*)d_in[1];
    const float* quats  = (const float*)d_in[2];
    const float* scales = (const float*)d_in[3];
    const float* opac   = (const float*)d_in[4];
    const float* rgbs   = (const float*)d_in[5];
    int n = in_sizes[4];
    if (n > NMAX) n = NMAX;

    gs_prep_sort<<<(n + 255) / 256, 256>>>(means, quats, scales, opac, rgbs, n);
    dim3 grid(W_ / 16, H_ / 16), block(16, 8);
    gs_render<<<grid, block>>>((float*)d_out, n);
}

// round 4
// speedup vs baseline: 1.5702x; 1.5702x over previous
#include <cuda_runtime.h>
#include <math.h>

#define W_ 256
#define H_ 256
#define NMAX 768
#define CUT_SIGMA 5.5412636f   // log(255): alpha >= 1/255  <=>  sigma <= log(255)

// depth-sorted gaussian data (written directly at rank)
__device__ float4 g_A[NMAX];   // mx, my, 0.5*conicA, 0.5*conicC
__device__ float4 g_B[NMAX];   // conicB, bias(=-log op), r, g
__device__ float  g_bv[NMAX];  // blue
__device__ float4 g_bb[NMAX];  // x0, x1, y0, y1

// Fused preprocess + stable rank sort; z staged in smem for the O(N) scan.
__global__ __launch_bounds__(256) void gs_prep_sort(
        const float* __restrict__ means,
        const float* __restrict__ quats,
        const float* __restrict__ scales,
        const float* __restrict__ opac_in,
        const float* __restrict__ rgbs,
        int n) {
    __shared__ float sz[NMAX];
    int tid = threadIdx.x;
    int i = blockIdx.x * blockDim.x + tid;

    for (int j = tid; j < n; j += 256)
        sz[j] = means[j*3+2];
    __syncthreads();

    if (i >= n) return;

    // stable ascending rank by z (tz = z + 8 monotone)
    float zi = sz[i];
    int rank = 0;
    #pragma unroll 8
    for (int j = 0; j < n; j++) {
        float zj = sz[j];
        rank += (zj < zi || (zj == zi && j < i)) ? 1 : 0;
    }

    float qw = quats[i*4+0], qx = quats[i*4+1], qy = quats[i*4+2], qz = quats[i*4+3];
    float inv = rsqrtf(qw*qw + qx*qx + qy*qy + qz*qz);
    float w = qw*inv, x = qx*inv, y = qy*inv, z = qz*inv;

    float R00 = 1.f - 2.f*(y*y + z*z), R01 = 2.f*(x*y - w*z), R02 = 2.f*(x*z + w*y);
    float R10 = 2.f*(x*y + w*z), R11 = 1.f - 2.f*(x*x + z*z), R12 = 2.f*(y*z - w*x);
    float R20 = 2.f*(x*z - w*y), R21 = 2.f*(y*z + w*x), R22 = 1.f - 2.f*(x*x + y*y);

    float sx = scales[i*3+0], sy = scales[i*3+1], szc = scales[i*3+2];
    float s0 = sx*sx, s1 = sy*sy, s2 = szc*szc;

    float C00 = R00*R00*s0 + R01*R01*s1 + R02*R02*s2;
    float C01 = R00*R10*s0 + R01*R11*s1 + R02*R12*s2;
    float C02 = R00*R20*s0 + R01*R21*s1 + R02*R22*s2;
    float C11 = R10*R10*s0 + R11*R11*s1 + R12*R12*s2;
    float C12 = R10*R20*s0 + R11*R21*s1 + R12*R22*s2;
    float C22 = R20*R20*s0 + R21*R21*s1 + R22*R22*s2;

    float tx = means[i*3+0], ty = means[i*3+1], tz = zi + 8.0f;
    const float f = 128.0f;
    float iz = 1.0f / tz;
    float j00 = f * iz;
    float j02 = -f * tx * iz * iz;
    float j12 = -f * ty * iz * iz;

    float a = j00*j00*C00 + 2.f*j00*j02*C02 + j02*j02*C22 + 0.3f;
    float b = j00*j00*C01 + j00*j12*C02 + j02*j00*C12 + j02*j12*C22;
    float c = j00*j00*C11 + 2.f*j00*j12*C12 + j12*j12*C22 + 0.3f;

    float det = a*c - b*b;
    float idet = 1.0f / det;
    float cA = c * idet, cB = -b * idet, cC = a * idet;

    float mx = f * tx * iz + 128.0f;
    float my = f * ty * iz + 128.0f;

    float op = 1.0f / (1.0f + __expf(-opac_in[i]));
    float cr = 1.0f / (1.0f + __expf(-rgbs[i*3+0]));
    float cg = 1.0f / (1.0f + __expf(-rgbs[i*3+1]));
    float cb = 1.0f / (1.0f + __expf(-rgbs[i*3+2]));

    float bias = -__logf(op);
    float tcut = CUT_SIGMA - bias;
    float ex, ey;
    if (tcut > 0.0f) {
        ex = sqrtf(2.0f * tcut * a) + 0.5f;
        ey = sqrtf(2.0f * tcut * c) + 0.5f;
    } else {
        ex = -1e30f; ey = -1e30f;
    }

    g_A[rank]  = make_float4(mx, my, 0.5f * cA, 0.5f * cC);
    g_B[rank]  = make_float4(cB, bias, cr, cg);
    g_bv[rank] = cb;
    g_bb[rank] = make_float4(mx - ex, mx + ex, my - ey, my + ey);
}

// 8x8 pixel tile per block, 64 threads, 1 px/thread. grid = 32x32 = 1024 blocks.
__global__ __launch_bounds__(64) void gs_render(float* __restrict__ out, int n) {
    __shared__ float4 sA[NMAX];
    __shared__ float4 sB[NMAX];
    __shared__ float  sBV[NMAX];
    __shared__ int s_w0cnt;
    __shared__ int s_cnt;

    const int tid = threadIdx.x;
    const int warp = tid >> 5, lane = tid & 31;
    const int tx = tid & 7, ty = tid >> 3;
    const int px0 = blockIdx.x * 8, py0 = blockIdx.y * 8;

    const float tlx = px0 + 0.5f, thx = px0 + 7.5f;
    const float tly = py0 + 0.5f, thy = py0 + 7.5f;

    // order-preserving compaction, 2 warps over contiguous chunks
    const int nIter = (n + 63) / 64;
    const int beg = warp * nIter * 32;
    int cnt = 0;
    for (int it = 0; it < nIter; it++) {
        int g = beg + it * 32 + lane;
        bool pred = false;
        if (g < n) {
            float4 bb = g_bb[g];
            pred = (bb.y >= tlx) & (bb.x <= thx) & (bb.w >= tly) & (bb.z <= thy);
        }
        cnt += __popc(__ballot_sync(0xffffffffu, pred));
    }
    if (lane == 0) {
        if (warp == 0) s_w0cnt = cnt;
        else           s_cnt   = cnt;   // temp: warp1 count
    }
    __syncthreads();
    int off = (warp == 0) ? 0 : s_w0cnt;
    const int tcnt = s_w0cnt + s_cnt;
    __syncthreads();

    for (int it = 0; it < nIter; it++) {
        int g = beg + it * 32 + lane;
        bool pred = false;
        if (g < n) {
            float4 bb = g_bb[g];
            pred = (bb.y >= tlx) & (bb.x <= thx) & (bb.w >= tly) & (bb.z <= thy);
        }
        unsigned m = __ballot_sync(0xffffffffu, pred);
        if (pred) {
            int slot = off + __popc(m & ((1u << lane) - 1u));
            sA[slot]  = g_A[g];
            sB[slot]  = g_B[g];
            sBV[slot] = g_bv[g];
        }
        off += __popc(m);
    }
    __syncthreads();

    const float pxc = px0 + tx + 0.5f;
    const float pyc = py0 + ty + 0.5f;

    float T = 1.0f, ar = 0.0f, ag = 0.0f, ab = 0.0f;
    #pragma unroll 4
    for (int k = 0; k < tcnt; k++) {
        float4 A = sA[k];
        float dx = pxc - A.x;
        float dy = pyc - A.y;
        float4 B = sB[k];
        float sigma = fmaf(A.z, dx*dx, fmaf(A.w, dy*dy, fmaf(B.x, dx*dy, B.y)));
        if (sigma <= CUT_SIGMA) {
            float al = fminf(0.999f, __expf(-sigma));
            float wt = T * al;
            ar = fmaf(wt, B.z, ar);
            ag = fmaf(wt, B.w, ag);
            ab = fmaf(wt, sBV[k], ab);
            T -= wt;
            if (T < 2e-6f) break;
        }
    }

    int p = (py0 + ty) * W_ + (px0 + tx);
    out[3*p + 0] = ar;
    out[3*p + 1] = ag;
    out[3*p + 2] = ab;
}

extern "C" void kernel_launch(void* const* d_in, const int* in_sizes, int n_in,
                              void* d_out, int out_size) {
    const float* means  = (const float*)d_in[1];
    const float* quats  = (const float*)d_in[2];
    const float* scales = (const float*)d_in[3];
    const float* opac   = (const float*)d_in[4];
    const float* rgbs   = (const float*)d_in[5];
    int n = in_sizes[4];
    if (n > NMAX) n = NMAX;

    gs_prep_sort<<<(n + 255) / 256, 256>>>(means, quats, scales, opac, rgbs, n);
    dim3 grid(W_ / 8, H_ / 8), block(64);
    gs_render<<<grid, block>>>((float*)d_out, n);
}